// round 3
// baseline (speedup 1.0000x reference)
#include <cuda_runtime.h>
#include <cuda_bf16.h>
#include <cstdint>

// ---------------------------------------------------------------------------
// Child-Sum Tree-LSTM over a complete 4-ary tree, depth 7.
//   N_NODES=21845, N_INTERNAL=5461, HID=IN=512.
// Plan:
//   1. zero leaf rows of h and c in d_out (d_out = [h(21845x512); c(21845x512)])
//   2. pack [W_iou; W_f] -> Wcat (2048x512), [b_iou; b_f] -> bcat
//   3. wx[5461x2048] = x[0:5461] @ Wcat^T + bcat        (big fp32 SGEMM)
//   4. level 6 (4096 nodes, all-leaf children): pure activation from wx
//   5. levels 5..0: iou_gemm (sum-gathered A), f_gemm (gathered A), combine
// All fp32 FFMA for exactness (rel_err threshold 1e-3; tensor-core tf32 is a
// later optimization once error margin is measured).
// ---------------------------------------------------------------------------

#define N_NODES    21845
#define N_INTERNAL 5461
#define HID        512
#define KDIM       512
#define NOUT       2048   // 1536 iou + 512 f

// Scratch (static device globals; allocation inside kernel_launch is banned)
__device__ float g_Wcat[NOUT * KDIM];          // 4 MB
__device__ float g_bcat[NOUT];
__device__ float g_wx[N_INTERNAL * NOUT];      // ~44.7 MB
__device__ float g_iou[1024 * 1536];           // 6 MB  (max level M = 1024)
__device__ float g_f[4096 * 512];              // 8 MB  (max 4*M = 4096 rows)

__device__ __forceinline__ float sigm(float v) { return 1.0f / (1.0f + expf(-v)); }

// ---------------------------------------------------------------------------
// zero leaf rows of h and c
// ---------------------------------------------------------------------------
__global__ void zero_leaves_kernel(float4* __restrict__ h4, float4* __restrict__ c4)
{
    const int cnt = (N_NODES - N_INTERNAL) * HID / 4;   // 2,097,152
    int i = blockIdx.x * blockDim.x + threadIdx.x;
    if (i < cnt) {
        float4 z = make_float4(0.f, 0.f, 0.f, 0.f);
        h4[i] = z;
        c4[i] = z;
    }
}

// ---------------------------------------------------------------------------
// pack W_iou / W_f into one contiguous (2048 x 512) matrix + bias vector
// ---------------------------------------------------------------------------
__global__ void pack_w_kernel(const float* __restrict__ W_iou, const float* __restrict__ b_iou,
                              const float* __restrict__ W_f,   const float* __restrict__ b_f)
{
    int i = blockIdx.x * blockDim.x + threadIdx.x;      // over 2048*512
    if (i < 1536 * KDIM) g_Wcat[i] = W_iou[i];
    else if (i < NOUT * KDIM) g_Wcat[i] = W_f[i - 1536 * KDIM];
    if (i < NOUT) g_bcat[i] = (i < 1536) ? b_iou[i] : b_f[i - 1536];
}

// ---------------------------------------------------------------------------
// Tiled fp32 GEMM, NT layout: C[M,N] = A'[M,K] * B[N,K]^T (+ optional col bias)
//   MODE 0: A'[m] = A[m]
//   MODE 1: A'[m] = A[idx[m]]                     (row gather)
//   MODE 2: A'[m] = sum_{j<4} A[idx[4m+j]]        (child-sum gather)
// Square tiles BM==BN; 256 threads; each thread computes TMxTN.
// ---------------------------------------------------------------------------
template<int BM, int BN, int BK, int TM, int TN, int MODE>
__global__ __launch_bounds__(256)
void sgemm_nt(const float* __restrict__ A, const float* __restrict__ B,
              float* __restrict__ C, const float* __restrict__ bias,
              const int* __restrict__ idx, int M, int N, int K)
{
    __shared__ float As[BK][BM];
    __shared__ float Bs[BK][BN];

    const int t  = threadIdx.x;                  // 0..255
    const int bm = blockIdx.y * BM;
    const int bn = blockIdx.x * BN;

    constexpr int KV = BK / 4;                   // float4 slots along K
    const int lr = t / KV;                       // tile row to load (< BM)
    const int lk = (t % KV) * 4;                 // k offset within tile

    const int tx = t % (BN / TN);
    const int ty = t / (BN / TN);

    float acc[TM][TN];
#pragma unroll
    for (int i = 0; i < TM; i++)
#pragma unroll
        for (int j = 0; j < TN; j++) acc[i][j] = 0.f;

    for (int k0 = 0; k0 < K; k0 += BK) {
        // --- load A tile ---
        float4 av = make_float4(0.f, 0.f, 0.f, 0.f);
        {
            int gm = bm + lr;
            if (gm < M) {
                if (MODE == 0) {
                    av = *reinterpret_cast<const float4*>(A + (size_t)gm * K + k0 + lk);
                } else if (MODE == 1) {
                    av = *reinterpret_cast<const float4*>(A + (size_t)idx[gm] * K + k0 + lk);
                } else {
#pragma unroll
                    for (int j = 0; j < 4; j++) {
                        const float4 v = *reinterpret_cast<const float4*>(
                            A + (size_t)idx[gm * 4 + j] * K + k0 + lk);
                        av.x += v.x; av.y += v.y; av.z += v.z; av.w += v.w;
                    }
                }
            }
        }
        As[lk + 0][lr] = av.x;
        As[lk + 1][lr] = av.y;
        As[lk + 2][lr] = av.z;
        As[lk + 3][lr] = av.w;

        // --- load B tile ---
        float4 bv = make_float4(0.f, 0.f, 0.f, 0.f);
        {
            int gn = bn + lr;
            if (gn < N)
                bv = *reinterpret_cast<const float4*>(B + (size_t)gn * K + k0 + lk);
        }
        Bs[lk + 0][lr] = bv.x;
        Bs[lk + 1][lr] = bv.y;
        Bs[lk + 2][lr] = bv.z;
        Bs[lk + 3][lr] = bv.w;

        __syncthreads();

#pragma unroll
        for (int kk = 0; kk < BK; kk++) {
            float a[TM], b[TN];
#pragma unroll
            for (int i = 0; i < TM; i++) a[i] = As[kk][ty * TM + i];
#pragma unroll
            for (int j = 0; j < TN; j++) b[j] = Bs[kk][tx * TN + j];
#pragma unroll
            for (int i = 0; i < TM; i++)
#pragma unroll
                for (int j = 0; j < TN; j++) acc[i][j] += a[i] * b[j];
        }
        __syncthreads();
    }

#pragma unroll
    for (int i = 0; i < TM; i++) {
        int r = bm + ty * TM + i;
        if (r >= M) continue;
#pragma unroll
        for (int j = 0; j < TN; j++) {
            int cc = bn + tx * TN + j;
            float v = acc[i][j];
            if (bias) v += bias[cc];
            C[(size_t)r * N + cc] = v;
        }
    }
}

// ---------------------------------------------------------------------------
// Level 6: children are leaves (h=c=0) -> iou = wx_iou, forget terms vanish.
// ---------------------------------------------------------------------------
__global__ __launch_bounds__(512)
void act6_kernel(float* __restrict__ h_arr, float* __restrict__ c_arr, int s)
{
    int n = blockIdx.x;
    int d = threadIdx.x;
    const float* wxp = g_wx + (size_t)(s + n) * NOUT;
    float i = sigm(wxp[d]);
    float o = sigm(wxp[512 + d]);
    float u = tanhf(wxp[1024 + d]);
    float c = i * u;
    c_arr[(size_t)(s + n) * HID + d] = c;
    h_arr[(size_t)(s + n) * HID + d] = o * tanhf(c);
}

// ---------------------------------------------------------------------------
// Generic level combine: uses g_iou (recurrent iou), g_f (recurrent f), g_wx.
//   iou_pre = g_iou[n] + wx_iou[s+n]
//   f_j     = g_f[n,j] + wx_f[s+n]          (NO sigmoid, per reference)
//   c_new   = sig(i)*tanh(u) + sum_j f_j * c[child_j]
//   h[s+n]  = sig(o)*tanh(c_new)
// ---------------------------------------------------------------------------
__global__ __launch_bounds__(512)
void combine_kernel(const int* __restrict__ children,
                    float* __restrict__ h_arr, float* __restrict__ c_arr, int s)
{
    int n = blockIdx.x;
    int d = threadIdx.x;
    const float* wxp  = g_wx  + (size_t)(s + n) * NOUT;
    const float* ioup = g_iou + (size_t)n * 1536;

    float i = sigm(ioup[d] + wxp[d]);
    float o = sigm(ioup[512 + d] + wxp[512 + d]);
    float u = tanhf(ioup[1024 + d] + wxp[1024 + d]);
    float wxf = wxp[1536 + d];

    float acc = i * u;
#pragma unroll
    for (int j = 0; j < 4; j++) {
        int ci = children[(s + n) * 4 + j];
        float fj = g_f[((size_t)n * 4 + j) * 512 + d] + wxf;
        acc += fj * c_arr[(size_t)ci * HID + d];
    }
    c_arr[(size_t)(s + n) * HID + d] = acc;
    h_arr[(size_t)(s + n) * HID + d] = o * tanhf(acc);
}

// ---------------------------------------------------------------------------
extern "C" void kernel_launch(void* const* d_in, const int* in_sizes, int n_in,
                              void* d_out, int out_size)
{
    const float* x      = (const float*)d_in[0];
    const int*   child  = (const int*)  d_in[1];
    const float* W_iou  = (const float*)d_in[2];
    const float* b_iou  = (const float*)d_in[3];
    const float* W_f    = (const float*)d_in[4];
    const float* b_f    = (const float*)d_in[5];
    const float* U_iou  = (const float*)d_in[6];
    const float* U_f    = (const float*)d_in[7];

    float* h_arr = (float*)d_out;                              // [21845 x 512]
    float* c_arr = (float*)d_out + (size_t)N_NODES * HID;      // [21845 x 512]

    // scratch symbol addresses (no allocation; these are static device globals)
    float *wx, *iou, *fbuf, *Wc, *bc;
    cudaGetSymbolAddress((void**)&wx,   g_wx);
    cudaGetSymbolAddress((void**)&iou,  g_iou);
    cudaGetSymbolAddress((void**)&fbuf, g_f);
    cudaGetSymbolAddress((void**)&Wc,   g_Wcat);
    cudaGetSymbolAddress((void**)&bc,   g_bcat);

    // 1. zero leaf rows of h and c (d_out is poisoned before timing)
    {
        float4* h4 = (float4*)(h_arr + (size_t)N_INTERNAL * HID);
        float4* c4 = (float4*)(c_arr + (size_t)N_INTERNAL * HID);
        int cnt = (N_NODES - N_INTERNAL) * HID / 4;
        zero_leaves_kernel<<<(cnt + 255) / 256, 256>>>(h4, c4);
    }

    // 2. pack weights
    pack_w_kernel<<<(NOUT * KDIM + 255) / 256, 256>>>(W_iou, b_iou, W_f, b_f);

    // 3. wx = x[0:NI] @ Wcat^T + bcat   (M=5461, N=2048, K=512)
    {
        dim3 grid(NOUT / 128, (N_INTERNAL + 127) / 128);
        sgemm_nt<128, 128, 8, 8, 8, 0><<<grid, 256>>>(
            x, Wc, wx, bc, nullptr, N_INTERNAL, NOUT, KDIM);
    }

    // 4. level 6: nodes [1365, 5461), pure activation
    act6_kernel<<<4096, 512>>>(h_arr, c_arr, 1365);

    // 5. levels 5..0
    for (int l = 5; l >= 0; --l) {
        int M = 1 << (2 * l);
        int s = (M - 1) / 3;
        const int* idx = child + (size_t)s * 4;

        // iou recurrence: g_iou[M x 1536] = (sum_j h[child_j]) @ U_iou^T
        {
            dim3 grid(1536 / 64, (M + 63) / 64);
            sgemm_nt<64, 64, 16, 4, 4, 2><<<grid, 256>>>(
                h_arr, U_iou, iou, nullptr, idx, M, 1536, KDIM);
        }
        // f recurrence: g_f[4M x 512] = h[child] @ U_f^T
        {
            dim3 grid(512 / 64, (4 * M + 63) / 64);
            sgemm_nt<64, 64, 16, 4, 4, 1><<<grid, 256>>>(
                h_arr, U_f, fbuf, nullptr, idx, 4 * M, 512, KDIM);
        }
        // gates + cell/hidden update
        combine_kernel<<<M, 512>>>(child, h_arr, c_arr, s);
    }
}